// round 2
// baseline (speedup 1.0000x reference)
#include <cuda_runtime.h>
#include <math.h>

#define Nn   100000
#define Ee   1600000
#define FIN  128
#define HH   64
#define CFf  16
#define GG   256

// Monotone mapping: float total order -> unsigned total order.
// Lets us do float max with a single u32 atomicMax (ptxas -> RED, no return).
__device__ __forceinline__ unsigned f2mono(float f) {
    unsigned u = __float_as_uint(f);
    return u ^ ((unsigned)((int)u >> 31) | 0x80000000u);
}
__device__ __forceinline__ float mono2f(unsigned u) {
    unsigned m = (u & 0x80000000u) ? (u ^ 0x80000000u) : ~u;
    return __uint_as_float(m);
}
// f2mono(-inf) == 0x007FFFFF  -> "empty segment" marker
#define EMPTY_MONO 0x007FFFFFu

// ---------------- device scratch (no cudaMalloc allowed) ----------------
__device__ unsigned g_agg[(size_t)Nn * FIN];   // reused: 128 cols (L1), 64 cols (L2/L3)
__device__ float    g_h1[(size_t)Nn * HH];
__device__ float    g_h2[(size_t)Nn * HH];
__device__ float    g_h3[(size_t)Nn * HH];
__device__ float    g_c[Nn];
__device__ float    g_e[Nn];
__device__ unsigned g_cmax[GG];
__device__ float    g_den[GG];
__device__ float    g_cnt[GG];
__device__ unsigned g_pooled[GG * HH];

// ---------------- helpers ----------------
__device__ __forceinline__ void red_max_guard(unsigned* p, float v) {
    unsigned m = f2mono(v);
    // cheap L2 read first; only RMW when it actually improves (monotone => safe)
    if (m > __ldcg(p)) atomicMax(p, m);
}

// ---------------- fills ----------------
__global__ void fill_u4(uint4* __restrict__ p, int n4, unsigned v) {
    int i = blockIdx.x * blockDim.x + threadIdx.x;
    if (i < n4) p[i] = make_uint4(v, v, v, v);
}

__global__ void init_small_kernel() {
    int i = blockIdx.x * blockDim.x + threadIdx.x;
    if (i < GG) { g_cmax[i] = EMPTY_MONO; g_den[i] = 0.f; g_cnt[i] = 0.f; }
    if (i < GG * HH) g_pooled[i] = EMPTY_MONO;
}

// ---------------- edge scatter-max ----------------
// One warp per edge, 4 features per lane (float4 gather from L2-resident x).
__global__ void scatter_max128(const float4* __restrict__ x4,
                               const int* __restrict__ ei,
                               unsigned* __restrict__ agg) {
    int t = blockIdx.x * blockDim.x + threadIdx.x;
    int e = t >> 5;
    if (e >= Ee) return;
    int lane = t & 31;
    int src = __ldg(&ei[e]);
    int dst = __ldg(&ei[Ee + e]);
    float4 v = __ldg(&x4[(size_t)src * 32 + lane]);
    unsigned* p = agg + (size_t)dst * 128 + lane * 4;
    red_max_guard(p + 0, v.x);
    red_max_guard(p + 1, v.y);
    red_max_guard(p + 2, v.z);
    red_max_guard(p + 3, v.w);
}

// 16 threads per edge for 64-wide features.
__global__ void scatter_max64(const float4* __restrict__ h4,
                              const int* __restrict__ ei,
                              unsigned* __restrict__ agg) {
    int t = blockIdx.x * blockDim.x + threadIdx.x;
    int e = t >> 4;
    if (e >= Ee) return;
    int s = t & 15;
    int src = __ldg(&ei[e]);
    int dst = __ldg(&ei[Ee + e]);
    float4 v = __ldg(&h4[(size_t)src * 16 + s]);
    unsigned* p = agg + (size_t)dst * 64 + s * 4;
    red_max_guard(p + 0, v.x);
    red_max_guard(p + 1, v.y);
    red_max_guard(p + 2, v.z);
    red_max_guard(p + 3, v.w);
}

// ---------------- fused SAGE layer GEMM ----------------
// out[n][j] = relu( sum_k dec(agg[n][k])*Wl[k][j] + x[n][k]*Wr[k][j] + b[j] )
// block: 256 threads, tile 64 nodes x 64 feats, per-thread 4x4 register tile.
template <int K>
__global__ void __launch_bounds__(256)
sage_gemm(const unsigned* __restrict__ aggm, const float* __restrict__ xin,
          const float* __restrict__ Wl, const float* __restrict__ blv,
          const float* __restrict__ Wr, float* __restrict__ out) {
    __shared__ float sA[64][65];  // transposed: [k][node], pad avoids bank conflicts
    __shared__ float sX[64][65];

    const int tid = threadIdx.x;
    const int tx = tid & 15;    // feature group (tx*4 .. tx*4+3)
    const int ty = tid >> 4;    // node group (ty*4 .. ty*4+3)
    const int node0 = blockIdx.x * 64;

    float acc[4][4];
#pragma unroll
    for (int i = 0; i < 4; i++)
#pragma unroll
        for (int j = 0; j < 4; j++) acc[i][j] = 0.f;

    for (int k0 = 0; k0 < K; k0 += 64) {
        __syncthreads();
#pragma unroll
        for (int t = tid; t < 64 * 64; t += 256) {
            int nn = t >> 6;
            int kk = t & 63;
            int node = node0 + nn;
            float a = 0.f, xv = 0.f;
            if (node < Nn) {
                unsigned u = aggm[(size_t)node * K + k0 + kk];
                a = (u == EMPTY_MONO) ? 0.f : mono2f(u);   // empty neighborhood -> 0
                xv = xin[(size_t)node * K + k0 + kk];
            }
            sA[kk][nn] = a;
            sX[kk][nn] = xv;
        }
        __syncthreads();

#pragma unroll 4
        for (int kk = 0; kk < 64; kk++) {
            const float4 wl = *(const float4*)&Wl[(size_t)(k0 + kk) * 64 + tx * 4];
            const float4 wr = *(const float4*)&Wr[(size_t)(k0 + kk) * 64 + tx * 4];
            float av[4], xv[4];
#pragma unroll
            for (int i = 0; i < 4; i++) {
                av[i] = sA[kk][ty * 4 + i];
                xv[i] = sX[kk][ty * 4 + i];
            }
#pragma unroll
            for (int i = 0; i < 4; i++) {
                acc[i][0] += av[i] * wl.x; acc[i][0] += xv[i] * wr.x;
                acc[i][1] += av[i] * wl.y; acc[i][1] += xv[i] * wr.y;
                acc[i][2] += av[i] * wl.z; acc[i][2] += xv[i] * wr.z;
                acc[i][3] += av[i] * wl.w; acc[i][3] += xv[i] * wr.w;
            }
        }
    }

    const float4 b4 = *(const float4*)&blv[tx * 4];
#pragma unroll
    for (int i = 0; i < 4; i++) {
        int node = node0 + ty * 4 + i;
        if (node < Nn) {
            float4 o;
            o.x = fmaxf(acc[i][0] + b4.x, 0.f);
            o.y = fmaxf(acc[i][1] + b4.y, 0.f);
            o.z = fmaxf(acc[i][2] + b4.z, 0.f);
            o.w = fmaxf(acc[i][3] + b4.w, 0.f);
            *(float4*)&out[(size_t)node * 64 + tx * 4] = o;
        }
    }
}

// ---------------- attention pooling ----------------
__global__ void c_kernel(const float4* __restrict__ clo4, const float* __restrict__ Wc,
                         const float* __restrict__ bc, const int* __restrict__ batch) {
    int i = blockIdx.x * blockDim.x + threadIdx.x;
    if (i >= Nn) return;
    float s = __ldg(&bc[0]);
#pragma unroll
    for (int q = 0; q < 4; q++) {
        float4 cv = __ldg(&clo4[(size_t)i * 4 + q]);
        float4 wv = *(const float4*)&Wc[q * 4];
        s += cv.x * wv.x + cv.y * wv.y + cv.z * wv.z + cv.w * wv.w;
    }
    g_c[i] = s;
    int b = batch[i];
    red_max_guard(&g_cmax[b], s);
}

__global__ void exp_kernel(const int* __restrict__ batch) {
    int i = blockIdx.x * blockDim.x + threadIdx.x;
    if (i >= Nn) return;
    int b = batch[i];
    float cm = mono2f(g_cmax[b]);
    float ev = expf(g_c[i] - cm);
    g_e[i] = ev;
    atomicAdd(&g_den[b], ev);
    atomicAdd(&g_cnt[b], 1.f);
}

__global__ void pool_kernel(const int* __restrict__ batch,
                            const float* __restrict__ h3) {
    int t = blockIdx.x * blockDim.x + threadIdx.x;
    if (t >= Nn * HH) return;
    int n = t >> 6;
    int f = t & 63;
    int b = batch[n];
    float p = g_e[n] / g_den[b] * g_cnt[b];
    float val = p * h3[(size_t)n * 64 + f];
    red_max_guard(&g_pooled[b * 64 + f], val);
}

__global__ void final_kernel(const float* __restrict__ Wa1, const float* __restrict__ ba1,
                             const float* __restrict__ Wa2, const float* __restrict__ ba2,
                             float* __restrict__ out) {
    int g = threadIdx.x;  // 256 threads, one per graph
    float s[16];
#pragma unroll
    for (int j = 0; j < 16; j++) s[j] = ba1[j];
    for (int f = 0; f < 64; f++) {
        unsigned u = g_pooled[g * 64 + f];
        float pv = (u == EMPTY_MONO) ? 0.f : mono2f(u);  // isfinite -> 0 on empty graphs
#pragma unroll
        for (int j = 0; j < 16; j++) s[j] += pv * Wa1[f * 16 + j];
    }
    float o = ba2[0];
#pragma unroll
    for (int j = 0; j < 16; j++) o += fmaxf(s[j], 0.f) * Wa2[j];
    out[g] = o;
}

// ---------------- launch ----------------
extern "C" void kernel_launch(void* const* d_in, const int* in_sizes, int n_in,
                              void* d_out, int out_size) {
    const float* x     = (const float*)d_in[0];
    const int*   ei    = (const int*)d_in[1];     // int32 (JAX x64 disabled)
    const int*   batch = (const int*)d_in[2];     // int32
    const float* clo   = (const float*)d_in[3];
    const float* W1l = (const float*)d_in[4];
    const float* b1l = (const float*)d_in[5];
    const float* W1r = (const float*)d_in[6];
    const float* W2l = (const float*)d_in[7];
    const float* b2l = (const float*)d_in[8];
    const float* W2r = (const float*)d_in[9];
    const float* W3l = (const float*)d_in[10];
    const float* b3l = (const float*)d_in[11];
    const float* W3r = (const float*)d_in[12];
    const float* Wc  = (const float*)d_in[13];
    const float* bc  = (const float*)d_in[14];
    const float* Wa1 = (const float*)d_in[15];
    const float* ba1 = (const float*)d_in[16];
    const float* Wa2 = (const float*)d_in[17];
    const float* ba2 = (const float*)d_in[18];
    float* out = (float*)d_out;

    unsigned* agg; cudaGetSymbolAddress((void**)&agg, g_agg);
    float* h1;     cudaGetSymbolAddress((void**)&h1, g_h1);
    float* h2;     cudaGetSymbolAddress((void**)&h2, g_h2);
    float* h3;     cudaGetSymbolAddress((void**)&h3, g_h3);

    const int TB = 256;

    // ---- layer 1 (K = 128) ----
    fill_u4<<<(Nn * 128 / 4 + TB - 1) / TB, TB>>>((uint4*)agg, Nn * 128 / 4, EMPTY_MONO);
    scatter_max128<<<(Ee * 32 + TB - 1) / TB, TB>>>((const float4*)x, ei, agg);
    sage_gemm<128><<<(Nn + 63) / 64, TB>>>(agg, x, W1l, b1l, W1r, h1);

    // ---- layer 2 (K = 64) ----
    fill_u4<<<(Nn * 64 / 4 + TB - 1) / TB, TB>>>((uint4*)agg, Nn * 64 / 4, EMPTY_MONO);
    scatter_max64<<<(Ee * 16 + TB - 1) / TB, TB>>>((const float4*)h1, ei, agg);
    sage_gemm<64><<<(Nn + 63) / 64, TB>>>(agg, h1, W2l, b2l, W2r, h2);

    // ---- layer 3 (K = 64) ----
    fill_u4<<<(Nn * 64 / 4 + TB - 1) / TB, TB>>>((uint4*)agg, Nn * 64 / 4, EMPTY_MONO);
    scatter_max64<<<(Ee * 16 + TB - 1) / TB, TB>>>((const float4*)h2, ei, agg);
    sage_gemm<64><<<(Nn + 63) / 64, TB>>>(agg, h2, W3l, b3l, W3r, h3);

    // ---- attention pooling ----
    init_small_kernel<<<(GG * HH + TB - 1) / TB, TB>>>();
    c_kernel<<<(Nn + TB - 1) / TB, TB>>>((const float4*)clo, Wc, bc, batch);
    exp_kernel<<<(Nn + TB - 1) / TB, TB>>>(batch);
    pool_kernel<<<(Nn * 64 + TB - 1) / TB, TB>>>(batch, h3);
    final_kernel<<<1, 256>>>(Wa1, ba1, Wa2, ba2, out);
}

// round 3
// speedup vs baseline: 2.3613x; 2.3613x over previous
#include <cuda_runtime.h>
#include <math.h>

#define Nn   100000
#define Ee   1600000
#define FIN  128
#define HH   64
#define GG   256
#define NEG_INF __int_as_float(0xff800000)

// Monotone mapping for the (tiny) pooling-stage float atomicMax.
__device__ __forceinline__ unsigned f2mono(float f) {
    unsigned u = __float_as_uint(f);
    return u ^ ((unsigned)((int)u >> 31) | 0x80000000u);
}
__device__ __forceinline__ float mono2f(unsigned u) {
    unsigned m = (u & 0x80000000u) ? (u ^ 0x80000000u) : ~u;
    return __uint_as_float(m);
}
#define EMPTY_MONO 0x007FFFFFu  // f2mono(-inf)

// ---------------- device scratch ----------------
__device__ int      g_deg[Nn];
__device__ int      g_rowptr[Nn];
__device__ int      g_fill[Nn];
__device__ int      g_csr[Ee];
__device__ int      g_bsum[128];
__device__ float    g_agg[(size_t)Nn * FIN];
__device__ float    g_h1[(size_t)Nn * HH];
__device__ float    g_h2[(size_t)Nn * HH];
__device__ float    g_h3[(size_t)Nn * HH];
__device__ float    g_c[Nn];
__device__ float    g_e[Nn];
__device__ unsigned g_cmax[GG];
__device__ float    g_den[GG];
__device__ float    g_cnt[GG];
__device__ unsigned g_pooled[GG * HH];

__device__ __forceinline__ void red_max_guard(unsigned* p, float v) {
    unsigned m = f2mono(v);
    if (m > __ldcg(p)) atomicMax(p, m);
}
__device__ __forceinline__ float4 max4(float4 a, float4 b) {
    return make_float4(fmaxf(a.x, b.x), fmaxf(a.y, b.y), fmaxf(a.z, b.z), fmaxf(a.w, b.w));
}

// ---------------- CSR build ----------------
__global__ void zero_deg_kernel() {
    int i = blockIdx.x * blockDim.x + threadIdx.x;
    if (i < Nn) { g_deg[i] = 0; g_fill[i] = 0; }
}

__global__ void hist_kernel(const int* __restrict__ ei) {
    int e = blockIdx.x * blockDim.x + threadIdx.x;
    if (e < Ee) atomicAdd(&g_deg[ei[Ee + e]], 1);
}

// 2-level exclusive scan over g_deg -> g_rowptr  (98 blocks x 1024)
__global__ void scan_a_kernel() {
    __shared__ int s[1024];
    int tid = threadIdx.x;
    int i = blockIdx.x * 1024 + tid;
    int v = (i < Nn) ? g_deg[i] : 0;
    s[tid] = v; __syncthreads();
#pragma unroll
    for (int off = 1; off < 1024; off <<= 1) {
        int t = (tid >= off) ? s[tid - off] : 0;
        __syncthreads();
        s[tid] += t;
        __syncthreads();
    }
    if (i < Nn) g_rowptr[i] = s[tid] - v;       // exclusive within block
    if (tid == 1023) g_bsum[blockIdx.x] = s[1023];
}

__global__ void scan_b_kernel(int nb) {  // 1 block, 128 threads
    __shared__ int s[128];
    int tid = threadIdx.x;
    int v = (tid < nb) ? g_bsum[tid] : 0;
    s[tid] = v; __syncthreads();
#pragma unroll
    for (int off = 1; off < 128; off <<= 1) {
        int t = (tid >= off) ? s[tid - off] : 0;
        __syncthreads();
        s[tid] += t;
        __syncthreads();
    }
    g_bsum[tid] = s[tid] - v;                   // exclusive block offsets
}

__global__ void scan_c_kernel() {
    int tid = threadIdx.x;
    int i = blockIdx.x * 1024 + tid;
    if (i < Nn) g_rowptr[i] += g_bsum[blockIdx.x];
}

__global__ void csr_scatter_kernel(const int* __restrict__ ei) {
    int e = blockIdx.x * blockDim.x + threadIdx.x;
    if (e >= Ee) return;
    int src = ei[e];
    int dst = ei[Ee + e];
    int pos = atomicAdd(&g_fill[dst], 1);
    g_csr[g_rowptr[dst] + pos] = src;
}

// ---------------- segmented max (gather, no atomics) ----------------
// One warp per node, float4 per lane (128 feats).
__global__ void agg_max128(const float4* __restrict__ x4, float4* __restrict__ agg4) {
    int t = blockIdx.x * blockDim.x + threadIdx.x;
    int w = t >> 5;
    if (w >= Nn) return;
    int lane = t & 31;
    int start = g_rowptr[w];
    int d = g_deg[w];
    float4 m = make_float4(NEG_INF, NEG_INF, NEG_INF, NEG_INF);
    int i = 0;
    for (; i + 4 <= d; i += 4) {
        int s0 = g_csr[start + i + 0];
        int s1 = g_csr[start + i + 1];
        int s2 = g_csr[start + i + 2];
        int s3 = g_csr[start + i + 3];
        float4 v0 = __ldg(&x4[(size_t)s0 * 32 + lane]);
        float4 v1 = __ldg(&x4[(size_t)s1 * 32 + lane]);
        float4 v2 = __ldg(&x4[(size_t)s2 * 32 + lane]);
        float4 v3 = __ldg(&x4[(size_t)s3 * 32 + lane]);
        m = max4(m, max4(max4(v0, v1), max4(v2, v3)));
    }
    for (; i < d; i++) {
        int s0 = g_csr[start + i];
        m = max4(m, __ldg(&x4[(size_t)s0 * 32 + lane]));
    }
    if (d == 0) m = make_float4(0.f, 0.f, 0.f, 0.f);  // empty neighborhood -> 0
    agg4[(size_t)w * 32 + lane] = m;
}

// Two nodes per warp (64 feats = 16 lanes x float4).
__global__ void agg_max64(const float4* __restrict__ h4, float4* __restrict__ agg4) {
    int t = blockIdx.x * blockDim.x + threadIdx.x;
    int w = t >> 5;
    int lane = t & 31;
    int node = w * 2 + (lane >> 4);
    if (node >= Nn) return;
    int s = lane & 15;
    int start = g_rowptr[node];
    int d = g_deg[node];
    float4 m = make_float4(NEG_INF, NEG_INF, NEG_INF, NEG_INF);
    int i = 0;
    for (; i + 4 <= d; i += 4) {
        int s0 = g_csr[start + i + 0];
        int s1 = g_csr[start + i + 1];
        int s2 = g_csr[start + i + 2];
        int s3 = g_csr[start + i + 3];
        float4 v0 = __ldg(&h4[(size_t)s0 * 16 + s]);
        float4 v1 = __ldg(&h4[(size_t)s1 * 16 + s]);
        float4 v2 = __ldg(&h4[(size_t)s2 * 16 + s]);
        float4 v3 = __ldg(&h4[(size_t)s3 * 16 + s]);
        m = max4(m, max4(max4(v0, v1), max4(v2, v3)));
    }
    for (; i < d; i++) {
        int s0 = g_csr[start + i];
        m = max4(m, __ldg(&h4[(size_t)s0 * 16 + s]));
    }
    if (d == 0) m = make_float4(0.f, 0.f, 0.f, 0.f);
    agg4[(size_t)node * 16 + s] = m;
}

// ---------------- fused SAGE layer GEMM ----------------
// out[n][j] = relu( sum_k agg[n][k]*Wl[k][j] + x[n][k]*Wr[k][j] + b[j] )
template <int K>
__global__ void __launch_bounds__(256)
sage_gemm(const float* __restrict__ agg, const float* __restrict__ xin,
          const float* __restrict__ Wl, const float* __restrict__ blv,
          const float* __restrict__ Wr, float* __restrict__ out) {
    __shared__ float sA[64][65];
    __shared__ float sX[64][65];

    const int tid = threadIdx.x;
    const int tx = tid & 15;
    const int ty = tid >> 4;
    const int node0 = blockIdx.x * 64;

    float acc[4][4];
#pragma unroll
    for (int i = 0; i < 4; i++)
#pragma unroll
        for (int j = 0; j < 4; j++) acc[i][j] = 0.f;

    for (int k0 = 0; k0 < K; k0 += 64) {
        __syncthreads();
#pragma unroll
        for (int t = tid; t < 64 * 64; t += 256) {
            int nn = t >> 6;
            int kk = t & 63;
            int node = node0 + nn;
            float a = 0.f, xv = 0.f;
            if (node < Nn) {
                a = agg[(size_t)node * K + k0 + kk];
                xv = xin[(size_t)node * K + k0 + kk];
            }
            sA[kk][nn] = a;
            sX[kk][nn] = xv;
        }
        __syncthreads();

#pragma unroll 4
        for (int kk = 0; kk < 64; kk++) {
            const float4 wl = *(const float4*)&Wl[(size_t)(k0 + kk) * 64 + tx * 4];
            const float4 wr = *(const float4*)&Wr[(size_t)(k0 + kk) * 64 + tx * 4];
            float av[4], xv[4];
#pragma unroll
            for (int i = 0; i < 4; i++) {
                av[i] = sA[kk][ty * 4 + i];
                xv[i] = sX[kk][ty * 4 + i];
            }
#pragma unroll
            for (int i = 0; i < 4; i++) {
                acc[i][0] += av[i] * wl.x; acc[i][0] += xv[i] * wr.x;
                acc[i][1] += av[i] * wl.y; acc[i][1] += xv[i] * wr.y;
                acc[i][2] += av[i] * wl.z; acc[i][2] += xv[i] * wr.z;
                acc[i][3] += av[i] * wl.w; acc[i][3] += xv[i] * wr.w;
            }
        }
    }

    const float4 b4 = *(const float4*)&blv[tx * 4];
#pragma unroll
    for (int i = 0; i < 4; i++) {
        int node = node0 + ty * 4 + i;
        if (node < Nn) {
            float4 o;
            o.x = fmaxf(acc[i][0] + b4.x, 0.f);
            o.y = fmaxf(acc[i][1] + b4.y, 0.f);
            o.z = fmaxf(acc[i][2] + b4.z, 0.f);
            o.w = fmaxf(acc[i][3] + b4.w, 0.f);
            *(float4*)&out[(size_t)node * 64 + tx * 4] = o;
        }
    }
}

// ---------------- attention pooling ----------------
__global__ void init_small_kernel() {
    int i = blockIdx.x * blockDim.x + threadIdx.x;
    if (i < GG) { g_cmax[i] = EMPTY_MONO; g_den[i] = 0.f; g_cnt[i] = 0.f; }
    if (i < GG * HH) g_pooled[i] = EMPTY_MONO;
}

__global__ void c_kernel(const float4* __restrict__ clo4, const float* __restrict__ Wc,
                         const float* __restrict__ bc, const int* __restrict__ batch) {
    int i = blockIdx.x * blockDim.x + threadIdx.x;
    if (i >= Nn) return;
    float s = __ldg(&bc[0]);
#pragma unroll
    for (int q = 0; q < 4; q++) {
        float4 cv = __ldg(&clo4[(size_t)i * 4 + q]);
        float4 wv = *(const float4*)&Wc[q * 4];
        s += cv.x * wv.x + cv.y * wv.y + cv.z * wv.z + cv.w * wv.w;
    }
    g_c[i] = s;
    red_max_guard(&g_cmax[batch[i]], s);
}

__global__ void exp_kernel(const int* __restrict__ batch) {
    int i = blockIdx.x * blockDim.x + threadIdx.x;
    if (i >= Nn) return;
    int b = batch[i];
    float ev = expf(g_c[i] - mono2f(g_cmax[b]));
    g_e[i] = ev;
    atomicAdd(&g_den[b], ev);
    atomicAdd(&g_cnt[b], 1.f);
}

__global__ void pool_kernel(const int* __restrict__ batch, const float* __restrict__ h3) {
    int t = blockIdx.x * blockDim.x + threadIdx.x;
    if (t >= Nn * HH) return;
    int n = t >> 6;
    int f = t & 63;
    int b = batch[n];
    float p = g_e[n] / g_den[b] * g_cnt[b];
    red_max_guard(&g_pooled[b * 64 + f], p * h3[(size_t)n * 64 + f]);
}

__global__ void final_kernel(const float* __restrict__ Wa1, const float* __restrict__ ba1,
                             const float* __restrict__ Wa2, const float* __restrict__ ba2,
                             float* __restrict__ out) {
    int g = threadIdx.x;
    float s[16];
#pragma unroll
    for (int j = 0; j < 16; j++) s[j] = ba1[j];
    for (int f = 0; f < 64; f++) {
        unsigned u = g_pooled[g * 64 + f];
        float pv = (u == EMPTY_MONO) ? 0.f : mono2f(u);
#pragma unroll
        for (int j = 0; j < 16; j++) s[j] += pv * Wa1[f * 16 + j];
    }
    float o = ba2[0];
#pragma unroll
    for (int j = 0; j < 16; j++) o += fmaxf(s[j], 0.f) * Wa2[j];
    out[g] = o;
}

// ---------------- launch ----------------
extern "C" void kernel_launch(void* const* d_in, const int* in_sizes, int n_in,
                              void* d_out, int out_size) {
    const float* x     = (const float*)d_in[0];
    const int*   ei    = (const int*)d_in[1];
    const int*   batch = (const int*)d_in[2];
    const float* clo   = (const float*)d_in[3];
    const float* W1l = (const float*)d_in[4];
    const float* b1l = (const float*)d_in[5];
    const float* W1r = (const float*)d_in[6];
    const float* W2l = (const float*)d_in[7];
    const float* b2l = (const float*)d_in[8];
    const float* W2r = (const float*)d_in[9];
    const float* W3l = (const float*)d_in[10];
    const float* b3l = (const float*)d_in[11];
    const float* W3r = (const float*)d_in[12];
    const float* Wc  = (const float*)d_in[13];
    const float* bc  = (const float*)d_in[14];
    const float* Wa1 = (const float*)d_in[15];
    const float* ba1 = (const float*)d_in[16];
    const float* Wa2 = (const float*)d_in[17];
    const float* ba2 = (const float*)d_in[18];
    float* out = (float*)d_out;

    float* agg; cudaGetSymbolAddress((void**)&agg, g_agg);
    float* h1;  cudaGetSymbolAddress((void**)&h1, g_h1);
    float* h2;  cudaGetSymbolAddress((void**)&h2, g_h2);
    float* h3;  cudaGetSymbolAddress((void**)&h3, g_h3);

    const int TB = 256;
    const int SCAN_BLOCKS = (Nn + 1023) / 1024;  // 98

    // ---- CSR build (by dst) ----
    zero_deg_kernel<<<(Nn + TB - 1) / TB, TB>>>();
    hist_kernel<<<(Ee + TB - 1) / TB, TB>>>(ei);
    scan_a_kernel<<<SCAN_BLOCKS, 1024>>>();
    scan_b_kernel<<<1, 128>>>(SCAN_BLOCKS);
    scan_c_kernel<<<SCAN_BLOCKS, 1024>>>();
    csr_scatter_kernel<<<(Ee + TB - 1) / TB, TB>>>(ei);

    // ---- layer 1 (K = 128) ----
    agg_max128<<<(Nn * 32 + TB - 1) / TB, TB>>>((const float4*)x, (float4*)agg);
    sage_gemm<128><<<(Nn + 63) / 64, TB>>>(agg, x, W1l, b1l, W1r, h1);

    // ---- layer 2 (K = 64) ----
    agg_max64<<<(Nn * 16 + TB - 1) / TB, TB>>>((const float4*)h1, (float4*)agg);
    sage_gemm<64><<<(Nn + 63) / 64, TB>>>(agg, h1, W2l, b2l, W2r, h2);

    // ---- layer 3 (K = 64) ----
    agg_max64<<<(Nn * 16 + TB - 1) / TB, TB>>>((const float4*)h2, (float4*)agg);
    sage_gemm<64><<<(Nn + 63) / 64, TB>>>(agg, h2, W3l, b3l, W3r, h3);

    // ---- attention pooling ----
    init_small_kernel<<<(GG * HH + TB - 1) / TB, TB>>>();
    c_kernel<<<(Nn + TB - 1) / TB, TB>>>((const float4*)clo, Wc, bc, batch);
    exp_kernel<<<(Nn + TB - 1) / TB, TB>>>(batch);
    pool_kernel<<<(Nn * 64 + TB - 1) / TB, TB>>>(batch, h3);
    final_kernel<<<1, 256>>>(Wa1, ba1, Wa2, ba2, out);
}

// round 4
// speedup vs baseline: 2.6222x; 1.1105x over previous
#include <cuda_runtime.h>
#include <math.h>

#define Nn   100000
#define Ee   1600000
#define FIN  128
#define HH   64
#define GG   256
#define NEG_INF __int_as_float(0xff800000)

typedef unsigned long long u64;

// ---------------- f32x2 helpers (PTX-only; ptxas never auto-fuses) ----------------
__device__ __forceinline__ u64 pack2(float lo, float hi) {
    u64 r; asm("mov.b64 %0, {%1, %2};" : "=l"(r) : "f"(lo), "f"(hi)); return r;
}
__device__ __forceinline__ void fma2(u64& d, u64 a, u64 b) {
    asm("fma.rn.f32x2 %0, %1, %2, %0;" : "+l"(d) : "l"(a), "l"(b));
}
__device__ __forceinline__ float2 unpack2(u64 v) {
    float2 f; asm("mov.b64 {%0, %1}, %2;" : "=f"(f.x), "=f"(f.y) : "l"(v)); return f;
}

// Monotone mapping for the (tiny) pooling-stage float atomicMax.
__device__ __forceinline__ unsigned f2mono(float f) {
    unsigned u = __float_as_uint(f);
    return u ^ ((unsigned)((int)u >> 31) | 0x80000000u);
}
__device__ __forceinline__ float mono2f(unsigned u) {
    unsigned m = (u & 0x80000000u) ? (u ^ 0x80000000u) : ~u;
    return __uint_as_float(m);
}
#define EMPTY_MONO 0x007FFFFFu  // f2mono(-inf)

// ---------------- device scratch ----------------
__device__ int      g_deg[Nn];
__device__ int      g_rowptr[Nn];
__device__ int      g_fill[Nn];
__device__ int      g_csr[Ee];
__device__ int      g_bsum[128];
__device__ float    g_agg[(size_t)Nn * FIN];
__device__ float    g_h1[(size_t)Nn * HH];
__device__ float    g_h2[(size_t)Nn * HH];
__device__ float    g_h3[(size_t)Nn * HH];
__device__ float    g_c[Nn];
__device__ float    g_e[Nn];
__device__ unsigned g_cmax[GG];
__device__ float    g_den[GG];
__device__ float    g_cnt[GG];
__device__ unsigned g_pooled[GG * HH];

__device__ __forceinline__ void red_max_guard(unsigned* p, float v) {
    unsigned m = f2mono(v);
    if (m > __ldcg(p)) atomicMax(p, m);
}
__device__ __forceinline__ float4 max4(float4 a, float4 b) {
    return make_float4(fmaxf(a.x, b.x), fmaxf(a.y, b.y), fmaxf(a.z, b.z), fmaxf(a.w, b.w));
}

// ---------------- CSR build ----------------
__global__ void zero_deg_kernel() {
    int i = blockIdx.x * blockDim.x + threadIdx.x;
    if (i < Nn) g_deg[i] = 0;
}

__global__ void hist_kernel(const int* __restrict__ ei) {
    int e = blockIdx.x * blockDim.x + threadIdx.x;
    if (e < Ee) atomicAdd(&g_deg[__ldg(&ei[Ee + e])], 1);
}

// Block-level exclusive scan (shfl), writes per-block exclusive prefix + block sums.
__global__ void scan_a_kernel() {
    __shared__ int wsum[32];
    int tid = threadIdx.x;
    int i = blockIdx.x * 1024 + tid;
    int v = (i < Nn) ? g_deg[i] : 0;
    int lane = tid & 31, wid = tid >> 5;
    int x = v;
#pragma unroll
    for (int o = 1; o < 32; o <<= 1) {
        int y = __shfl_up_sync(0xffffffffu, x, o);
        if (lane >= o) x += y;
    }
    if (lane == 31) wsum[wid] = x;
    __syncthreads();
    if (wid == 0) {
        int w = wsum[lane];
        int xx = w;
#pragma unroll
        for (int o = 1; o < 32; o <<= 1) {
            int y = __shfl_up_sync(0xffffffffu, xx, o);
            if (lane >= o) xx += y;
        }
        wsum[lane] = xx - w;   // exclusive warp offsets
    }
    __syncthreads();
    int excl = x - v + wsum[wid];
    if (i < Nn) g_rowptr[i] = excl;
    if (tid == 1023) g_bsum[blockIdx.x] = excl + v;
}

// Adds block offsets (computed in-block, no separate scan_b launch); seeds g_fill.
__global__ void scan_c_kernel(int nb) {
    __shared__ int ws[4];
    __shared__ int soff;
    int tid = threadIdx.x;
    if (tid < 128) {
        int v = (tid < nb && tid < blockIdx.x) ? g_bsum[tid] : 0;
#pragma unroll
        for (int o = 16; o > 0; o >>= 1) v += __shfl_down_sync(0xffffffffu, v, o);
        if ((tid & 31) == 0) ws[tid >> 5] = v;
    }
    __syncthreads();
    if (tid == 0) soff = ws[0] + ws[1] + ws[2] + ws[3];
    __syncthreads();
    int i = blockIdx.x * 1024 + tid;
    if (i < Nn) {
        int r = g_rowptr[i] + soff;
        g_rowptr[i] = r;
        g_fill[i] = r;          // csr_scatter bumps this directly
    }
}

__global__ void csr_scatter_kernel(const int* __restrict__ ei) {
    int e = blockIdx.x * blockDim.x + threadIdx.x;
    if (e >= Ee) return;
    int src = __ldg(&ei[e]);
    int dst = __ldg(&ei[Ee + e]);
    int pos = atomicAdd(&g_fill[dst], 1);
    g_csr[pos] = src;
}

// ---------------- segmented max (gather, no atomics) ----------------
__global__ void agg_max128(const float4* __restrict__ x4, float4* __restrict__ agg4) {
    int t = blockIdx.x * blockDim.x + threadIdx.x;
    int w = t >> 5;
    if (w >= Nn) return;
    int lane = t & 31;
    int start = g_rowptr[w];
    int d = g_deg[w];
    float4 m = make_float4(NEG_INF, NEG_INF, NEG_INF, NEG_INF);
    int i = 0;
    for (; i + 4 <= d; i += 4) {
        int s0 = g_csr[start + i + 0];
        int s1 = g_csr[start + i + 1];
        int s2 = g_csr[start + i + 2];
        int s3 = g_csr[start + i + 3];
        float4 v0 = __ldg(&x4[(size_t)s0 * 32 + lane]);
        float4 v1 = __ldg(&x4[(size_t)s1 * 32 + lane]);
        float4 v2 = __ldg(&x4[(size_t)s2 * 32 + lane]);
        float4 v3 = __ldg(&x4[(size_t)s3 * 32 + lane]);
        m = max4(m, max4(max4(v0, v1), max4(v2, v3)));
    }
    for (; i < d; i++)
        m = max4(m, __ldg(&x4[(size_t)g_csr[start + i] * 32 + lane]));
    if (d == 0) m = make_float4(0.f, 0.f, 0.f, 0.f);
    agg4[(size_t)w * 32 + lane] = m;
}

__global__ void agg_max64(const float4* __restrict__ h4, float4* __restrict__ agg4) {
    int t = blockIdx.x * blockDim.x + threadIdx.x;
    int w = t >> 5;
    int lane = t & 31;
    int node = w * 2 + (lane >> 4);
    if (node >= Nn) return;
    int s = lane & 15;
    int start = g_rowptr[node];
    int d = g_deg[node];
    float4 m = make_float4(NEG_INF, NEG_INF, NEG_INF, NEG_INF);
    int i = 0;
    for (; i + 4 <= d; i += 4) {
        int s0 = g_csr[start + i + 0];
        int s1 = g_csr[start + i + 1];
        int s2 = g_csr[start + i + 2];
        int s3 = g_csr[start + i + 3];
        float4 v0 = __ldg(&h4[(size_t)s0 * 16 + s]);
        float4 v1 = __ldg(&h4[(size_t)s1 * 16 + s]);
        float4 v2 = __ldg(&h4[(size_t)s2 * 16 + s]);
        float4 v3 = __ldg(&h4[(size_t)s3 * 16 + s]);
        m = max4(m, max4(max4(v0, v1), max4(v2, v3)));
    }
    for (; i < d; i++)
        m = max4(m, __ldg(&h4[(size_t)g_csr[start + i] * 16 + s]));
    if (d == 0) m = make_float4(0.f, 0.f, 0.f, 0.f);
    agg4[(size_t)node * 16 + s] = m;
}

// ---------------- fused SAGE layer GEMM (f32x2 packed FMA) ----------------
// out[n][j] = relu( sum_k agg[n][k]*Wl[k][j] + x[n][k]*Wr[k][j] + b[j] )
// 256 threads; tile 64 nodes x 64 out-feats; thread tile 4 nodes x 4 feats (2 f32x2 pairs).
template <int K>
__global__ void __launch_bounds__(256)
sage_gemm(const float* __restrict__ agg, const float* __restrict__ xin,
          const float* __restrict__ Wl, const float* __restrict__ blv,
          const float* __restrict__ Wr, float* __restrict__ out) {
    __shared__ float sA[64][68];   // node-major; 68-float stride keeps 16B alignment
    __shared__ float sX[64][68];

    const int tid = threadIdx.x;
    const int tx = tid & 15;     // output feature group: j = tx*4 .. tx*4+3
    const int ty = tid >> 4;     // node group: n = ty*4 .. ty*4+3
    const int node0 = blockIdx.x * 64;

    u64 acc[4][2];
#pragma unroll
    for (int i = 0; i < 4; i++) { acc[i][0] = 0ULL; acc[i][1] = 0ULL; }

    for (int k0 = 0; k0 < K; k0 += 64) {
        __syncthreads();
        // stage: float4 coalesced global reads, conflict-free float4 smem stores
#pragma unroll
        for (int t = tid; t < 64 * 16; t += 256) {
            int nn = t >> 4;
            int ck = t & 15;
            int node = node0 + nn;
            float4 a = make_float4(0.f, 0.f, 0.f, 0.f);
            float4 xv = a;
            if (node < Nn) {
                a  = *(const float4*)&agg[(size_t)node * K + k0 + ck * 4];
                xv = *(const float4*)&xin[(size_t)node * K + k0 + ck * 4];
            }
            *(float4*)&sA[nn][ck * 4] = a;
            *(float4*)&sX[nn][ck * 4] = xv;
        }
        __syncthreads();

#pragma unroll 8
        for (int kk = 0; kk < 64; kk++) {
            // weights arrive pre-paired for f32x2 via 128-bit loads
            const ulonglong2 wl2 = *(const ulonglong2*)&Wl[(size_t)(k0 + kk) * 64 + tx * 4];
            const ulonglong2 wr2 = *(const ulonglong2*)&Wr[(size_t)(k0 + kk) * 64 + tx * 4];
#pragma unroll
            for (int i = 0; i < 4; i++) {
                float a  = sA[ty * 4 + i][kk];   // warp-broadcast LDS
                float xv = sX[ty * 4 + i][kk];
                u64 a2 = pack2(a, a);
                u64 x2 = pack2(xv, xv);
                fma2(acc[i][0], a2, wl2.x);
                fma2(acc[i][1], a2, wl2.y);
                fma2(acc[i][0], x2, wr2.x);
                fma2(acc[i][1], x2, wr2.y);
            }
        }
    }

    const float4 b4 = *(const float4*)&blv[tx * 4];
#pragma unroll
    for (int i = 0; i < 4; i++) {
        int node = node0 + ty * 4 + i;
        if (node < Nn) {
            float2 lo = unpack2(acc[i][0]);
            float2 hi = unpack2(acc[i][1]);
            float4 o;
            o.x = fmaxf(lo.x + b4.x, 0.f);
            o.y = fmaxf(lo.y + b4.y, 0.f);
            o.z = fmaxf(hi.x + b4.z, 0.f);
            o.w = fmaxf(hi.y + b4.w, 0.f);
            *(float4*)&out[(size_t)node * 64 + tx * 4] = o;
        }
    }
}

// ---------------- attention pooling ----------------
__global__ void init_small_kernel() {
    int i = blockIdx.x * blockDim.x + threadIdx.x;
    if (i < GG) { g_cmax[i] = EMPTY_MONO; g_den[i] = 0.f; g_cnt[i] = 0.f; }
    if (i < GG * HH) g_pooled[i] = EMPTY_MONO;
}

__global__ void c_kernel(const float4* __restrict__ clo4, const float* __restrict__ Wc,
                         const float* __restrict__ bc, const int* __restrict__ batch) {
    int i = blockIdx.x * blockDim.x + threadIdx.x;
    if (i >= Nn) return;
    float s = __ldg(&bc[0]);
#pragma unroll
    for (int q = 0; q < 4; q++) {
        float4 cv = __ldg(&clo4[(size_t)i * 4 + q]);
        float4 wv = *(const float4*)&Wc[q * 4];
        s += cv.x * wv.x + cv.y * wv.y + cv.z * wv.z + cv.w * wv.w;
    }
    g_c[i] = s;
    red_max_guard(&g_cmax[batch[i]], s);
}

__global__ void exp_kernel(const int* __restrict__ batch) {
    int i = blockIdx.x * blockDim.x + threadIdx.x;
    if (i >= Nn) return;
    int b = batch[i];
    float ev = expf(g_c[i] - mono2f(g_cmax[b]));
    g_e[i] = ev;
    atomicAdd(&g_den[b], ev);
    atomicAdd(&g_cnt[b], 1.f);
}

__global__ void pool_kernel(const int* __restrict__ batch, const float* __restrict__ h3) {
    int t = blockIdx.x * blockDim.x + threadIdx.x;
    if (t >= Nn * HH) return;
    int n = t >> 6;
    int f = t & 63;
    int b = batch[n];
    float p = g_e[n] / g_den[b] * g_cnt[b];
    red_max_guard(&g_pooled[b * 64 + f], p * h3[(size_t)n * 64 + f]);
}

__global__ void final_kernel(const float* __restrict__ Wa1, const float* __restrict__ ba1,
                             const float* __restrict__ Wa2, const float* __restrict__ ba2,
                             float* __restrict__ out) {
    int g = threadIdx.x;
    float s[16];
#pragma unroll
    for (int j = 0; j < 16; j++) s[j] = ba1[j];
    for (int f = 0; f < 64; f++) {
        unsigned u = g_pooled[g * 64 + f];
        float pv = (u == EMPTY_MONO) ? 0.f : mono2f(u);
#pragma unroll
        for (int j = 0; j < 16; j++) s[j] += pv * Wa1[f * 16 + j];
    }
    float o = ba2[0];
#pragma unroll
    for (int j = 0; j < 16; j++) o += fmaxf(s[j], 0.f) * Wa2[j];
    out[g] = o;
}

// ---------------- launch ----------------
extern "C" void kernel_launch(void* const* d_in, const int* in_sizes, int n_in,
                              void* d_out, int out_size) {
    const float* x     = (const float*)d_in[0];
    const int*   ei    = (const int*)d_in[1];
    const int*   batch = (const int*)d_in[2];
    const float* clo   = (const float*)d_in[3];
    const float* W1l = (const float*)d_in[4];
    const float* b1l = (const float*)d_in[5];
    const float* W1r = (const float*)d_in[6];
    const float* W2l = (const float*)d_in[7];
    const float* b2l = (const float*)d_in[8];
    const float* W2r = (const float*)d_in[9];
    const float* W3l = (const float*)d_in[10];
    const float* b3l = (const float*)d_in[11];
    const float* W3r = (const float*)d_in[12];
    const float* Wc  = (const float*)d_in[13];
    const float* bc  = (const float*)d_in[14];
    const float* Wa1 = (const float*)d_in[15];
    const float* ba1 = (const float*)d_in[16];
    const float* Wa2 = (const float*)d_in[17];
    const float* ba2 = (const float*)d_in[18];
    float* out = (float*)d_out;

    float* agg; cudaGetSymbolAddress((void**)&agg, g_agg);
    float* h1;  cudaGetSymbolAddress((void**)&h1, g_h1);
    float* h2;  cudaGetSymbolAddress((void**)&h2, g_h2);
    float* h3;  cudaGetSymbolAddress((void**)&h3, g_h3);

    const int TB = 256;
    const int SCAN_BLOCKS = (Nn + 1023) / 1024;  // 98

    // ---- CSR build (by dst) ----
    zero_deg_kernel<<<(Nn + TB - 1) / TB, TB>>>();
    hist_kernel<<<(Ee + TB - 1) / TB, TB>>>(ei);
    scan_a_kernel<<<SCAN_BLOCKS, 1024>>>();
    scan_c_kernel<<<SCAN_BLOCKS, 1024>>>(SCAN_BLOCKS);
    csr_scatter_kernel<<<(Ee + TB - 1) / TB, TB>>>(ei);

    // ---- layer 1 (K = 128) ----
    agg_max128<<<(Nn * 32 + TB - 1) / TB, TB>>>((const float4*)x, (float4*)agg);
    sage_gemm<128><<<(Nn + 63) / 64, TB>>>(agg, x, W1l, b1l, W1r, h1);

    // ---- layer 2 (K = 64) ----
    agg_max64<<<(Nn * 16 + TB - 1) / TB, TB>>>((const float4*)h1, (float4*)agg);
    sage_gemm<64><<<(Nn + 63) / 64, TB>>>(agg, h1, W2l, b2l, W2r, h2);

    // ---- layer 3 (K = 64) ----
    agg_max64<<<(Nn * 16 + TB - 1) / TB, TB>>>((const float4*)h2, (float4*)agg);
    sage_gemm<64><<<(Nn + 63) / 64, TB>>>(agg, h2, W3l, b3l, W3r, h3);

    // ---- attention pooling ----
    init_small_kernel<<<(GG * HH + TB - 1) / TB, TB>>>();
    c_kernel<<<(Nn + TB - 1) / TB, TB>>>((const float4*)clo, Wc, bc, batch);
    exp_kernel<<<(Nn + TB - 1) / TB, TB>>>(batch);
    pool_kernel<<<(Nn * 64 + TB - 1) / TB, TB>>>(batch, h3);
    final_kernel<<<1, 256>>>(Wa1, ba1, Wa2, ba2, out);
}

// round 5
// speedup vs baseline: 3.3869x; 1.2916x over previous
#include <cuda_runtime.h>
#include <math.h>

#define Nn   100000
#define Ee   1600000
#define FIN  128
#define HH   64
#define GG   256
#define NEG_INF __int_as_float(0xff800000)

typedef unsigned long long u64;

// ---------------- f32x2 helpers (PTX-only; ptxas never auto-fuses) ----------------
__device__ __forceinline__ u64 pack2(float lo, float hi) {
    u64 r; asm("mov.b64 %0, {%1, %2};" : "=l"(r) : "f"(lo), "f"(hi)); return r;
}
__device__ __forceinline__ void fma2(u64& d, u64 a, u64 b) {
    asm("fma.rn.f32x2 %0, %1, %2, %0;" : "+l"(d) : "l"(a), "l"(b));
}
__device__ __forceinline__ float2 unpack2(u64 v) {
    float2 f; asm("mov.b64 {%0, %1}, %2;" : "=f"(f.x), "=f"(f.y) : "l"(v)); return f;
}

// ---------------- device scratch ----------------
__device__ int      g_deg[Nn];
__device__ int      g_rowptr[Nn];
__device__ int      g_fill[Nn];
__device__ int      g_csr[Ee];
__device__ int      g_bsum[128];
__device__ float    g_agg[(size_t)Nn * FIN];
__device__ float    g_h1[(size_t)Nn * HH];
__device__ float    g_h2[(size_t)Nn * HH];
__device__ float    g_h3[(size_t)Nn * HH];
__device__ float    g_c[Nn];
__device__ float    g_e[Nn];

__device__ __forceinline__ float4 max4(float4 a, float4 b) {
    return make_float4(fmaxf(a.x, b.x), fmaxf(a.y, b.y), fmaxf(a.z, b.z), fmaxf(a.w, b.w));
}
__device__ __forceinline__ float2 max2(float2 a, float2 b) {
    return make_float2(fmaxf(a.x, b.x), fmaxf(a.y, b.y));
}

// ---------------- CSR build ----------------
__global__ void zero_deg_kernel() {
    int i = blockIdx.x * blockDim.x + threadIdx.x;
    if (i < Nn) g_deg[i] = 0;
}

__global__ void hist_kernel(const int* __restrict__ ei) {
    int e = blockIdx.x * blockDim.x + threadIdx.x;
    if (e < Ee) atomicAdd(&g_deg[__ldg(&ei[Ee + e])], 1);
}

__global__ void scan_a_kernel() {
    __shared__ int wsum[32];
    int tid = threadIdx.x;
    int i = blockIdx.x * 1024 + tid;
    int v = (i < Nn) ? g_deg[i] : 0;
    int lane = tid & 31, wid = tid >> 5;
    int x = v;
#pragma unroll
    for (int o = 1; o < 32; o <<= 1) {
        int y = __shfl_up_sync(0xffffffffu, x, o);
        if (lane >= o) x += y;
    }
    if (lane == 31) wsum[wid] = x;
    __syncthreads();
    if (wid == 0) {
        int w = wsum[lane];
        int xx = w;
#pragma unroll
        for (int o = 1; o < 32; o <<= 1) {
            int y = __shfl_up_sync(0xffffffffu, xx, o);
            if (lane >= o) xx += y;
        }
        wsum[lane] = xx - w;
    }
    __syncthreads();
    int excl = x - v + wsum[wid];
    if (i < Nn) g_rowptr[i] = excl;
    if (tid == 1023) g_bsum[blockIdx.x] = excl + v;
}

__global__ void scan_c_kernel(int nb) {
    __shared__ int ws[4];
    __shared__ int soff;
    int tid = threadIdx.x;
    if (tid < 128) {
        int v = (tid < nb && tid < blockIdx.x) ? g_bsum[tid] : 0;
#pragma unroll
        for (int o = 16; o > 0; o >>= 1) v += __shfl_down_sync(0xffffffffu, v, o);
        if ((tid & 31) == 0) ws[tid >> 5] = v;
    }
    __syncthreads();
    if (tid == 0) soff = ws[0] + ws[1] + ws[2] + ws[3];
    __syncthreads();
    int i = blockIdx.x * 1024 + tid;
    if (i < Nn) {
        int r = g_rowptr[i] + soff;
        g_rowptr[i] = r;
        g_fill[i] = r;
    }
}

__global__ void csr_scatter_kernel(const int* __restrict__ ei) {
    int e = blockIdx.x * blockDim.x + threadIdx.x;
    if (e >= Ee) return;
    int src = __ldg(&ei[e]);
    int dst = __ldg(&ei[Ee + e]);
    int pos = atomicAdd(&g_fill[dst], 1);
    g_csr[pos] = src;
}

// ---------------- segmented max (gather, MLP=8) ----------------
// One warp per node, float4 per lane (128 feats).
__global__ void agg_max128(const float4* __restrict__ x4, float4* __restrict__ agg4) {
    int t = blockIdx.x * blockDim.x + threadIdx.x;
    int w = t >> 5;
    if (w >= Nn) return;
    int lane = t & 31;
    int start = g_rowptr[w];
    int d = g_deg[w];
    float4 m = make_float4(NEG_INF, NEG_INF, NEG_INF, NEG_INF);
    int i = 0;
    for (; i + 8 <= d; i += 8) {
        int idx[8];
#pragma unroll
        for (int j = 0; j < 8; j++) idx[j] = g_csr[start + i + j];
        float4 v[8];
#pragma unroll
        for (int j = 0; j < 8; j++) v[j] = __ldg(&x4[(size_t)idx[j] * 32 + lane]);
#pragma unroll
        for (int j = 0; j < 8; j++) m = max4(m, v[j]);
    }
    if (i + 4 <= d) {
        int idx[4];
#pragma unroll
        for (int j = 0; j < 4; j++) idx[j] = g_csr[start + i + j];
        float4 v[4];
#pragma unroll
        for (int j = 0; j < 4; j++) v[j] = __ldg(&x4[(size_t)idx[j] * 32 + lane]);
#pragma unroll
        for (int j = 0; j < 4; j++) m = max4(m, v[j]);
        i += 4;
    }
    for (; i < d; i++)
        m = max4(m, __ldg(&x4[(size_t)g_csr[start + i] * 32 + lane]));
    if (d == 0) m = make_float4(0.f, 0.f, 0.f, 0.f);
    agg4[(size_t)w * 32 + lane] = m;
}

// One warp per node, float2 per lane (64 feats). Uniform trip count.
__global__ void agg_max64(const float2* __restrict__ h2, float2* __restrict__ agg2) {
    int t = blockIdx.x * blockDim.x + threadIdx.x;
    int w = t >> 5;
    if (w >= Nn) return;
    int lane = t & 31;
    int start = g_rowptr[w];
    int d = g_deg[w];
    float2 m = make_float2(NEG_INF, NEG_INF);
    int i = 0;
    for (; i + 8 <= d; i += 8) {
        int idx[8];
#pragma unroll
        for (int j = 0; j < 8; j++) idx[j] = g_csr[start + i + j];
        float2 v[8];
#pragma unroll
        for (int j = 0; j < 8; j++) v[j] = __ldg(&h2[(size_t)idx[j] * 32 + lane]);
#pragma unroll
        for (int j = 0; j < 8; j++) m = max2(m, v[j]);
    }
    if (i + 4 <= d) {
        int idx[4];
#pragma unroll
        for (int j = 0; j < 4; j++) idx[j] = g_csr[start + i + j];
        float2 v[4];
#pragma unroll
        for (int j = 0; j < 4; j++) v[j] = __ldg(&h2[(size_t)idx[j] * 32 + lane]);
#pragma unroll
        for (int j = 0; j < 4; j++) m = max2(m, v[j]);
        i += 4;
    }
    for (; i < d; i++)
        m = max2(m, __ldg(&h2[(size_t)g_csr[start + i] * 32 + lane]));
    if (d == 0) m = make_float2(0.f, 0.f);
    agg2[(size_t)w * 32 + lane] = m;
}

// ---------------- fused SAGE layer GEMM (f32x2 packed FMA) ----------------
template <int K>
__global__ void __launch_bounds__(256)
sage_gemm(const float* __restrict__ agg, const float* __restrict__ xin,
          const float* __restrict__ Wl, const float* __restrict__ blv,
          const float* __restrict__ Wr, float* __restrict__ out) {
    __shared__ float sA[64][68];
    __shared__ float sX[64][68];

    const int tid = threadIdx.x;
    const int tx = tid & 15;
    const int ty = tid >> 4;
    const int node0 = blockIdx.x * 64;

    u64 acc[4][2];
#pragma unroll
    for (int i = 0; i < 4; i++) { acc[i][0] = 0ULL; acc[i][1] = 0ULL; }

    for (int k0 = 0; k0 < K; k0 += 64) {
        __syncthreads();
#pragma unroll
        for (int t = tid; t < 64 * 16; t += 256) {
            int nn = t >> 4;
            int ck = t & 15;
            int node = node0 + nn;
            float4 a = make_float4(0.f, 0.f, 0.f, 0.f);
            float4 xv = a;
            if (node < Nn) {
                a  = *(const float4*)&agg[(size_t)node * K + k0 + ck * 4];
                xv = *(const float4*)&xin[(size_t)node * K + k0 + ck * 4];
            }
            *(float4*)&sA[nn][ck * 4] = a;
            *(float4*)&sX[nn][ck * 4] = xv;
        }
        __syncthreads();

#pragma unroll 8
        for (int kk = 0; kk < 64; kk++) {
            const ulonglong2 wl2 = *(const ulonglong2*)&Wl[(size_t)(k0 + kk) * 64 + tx * 4];
            const ulonglong2 wr2 = *(const ulonglong2*)&Wr[(size_t)(k0 + kk) * 64 + tx * 4];
#pragma unroll
            for (int i = 0; i < 4; i++) {
                float a  = sA[ty * 4 + i][kk];
                float xv = sX[ty * 4 + i][kk];
                u64 a2 = pack2(a, a);
                u64 x2 = pack2(xv, xv);
                fma2(acc[i][0], a2, wl2.x);
                fma2(acc[i][1], a2, wl2.y);
                fma2(acc[i][0], x2, wr2.x);
                fma2(acc[i][1], x2, wr2.y);
            }
        }
    }

    const float4 b4 = *(const float4*)&blv[tx * 4];
#pragma unroll
    for (int i = 0; i < 4; i++) {
        int node = node0 + ty * 4 + i;
        if (node < Nn) {
            float2 lo = unpack2(acc[i][0]);
            float2 hi = unpack2(acc[i][1]);
            float4 o;
            o.x = fmaxf(lo.x + b4.x, 0.f);
            o.y = fmaxf(lo.y + b4.y, 0.f);
            o.z = fmaxf(hi.x + b4.z, 0.f);
            o.w = fmaxf(hi.y + b4.w, 0.f);
            *(float4*)&out[(size_t)node * 64 + tx * 4] = o;
        }
    }
}

// ---------------- fused attention pooling: one block per graph ----------------
// batch is SORTED, so each graph's nodes are a contiguous range found by binary search.
// Does: c = clo@Wc+bc, per-graph softmax (max/exp/sum), weighted max-pool over h3,
// and the final 64->16->1 MLP. No global atomics, no init kernels.
__global__ void __launch_bounds__(256)
fused_pool_kernel(const float4* __restrict__ clo4, const float* __restrict__ Wc,
                  const float* __restrict__ bc, const int* __restrict__ batch,
                  const float* __restrict__ h3,
                  const float* __restrict__ Wa1, const float* __restrict__ ba1,
                  const float* __restrict__ Wa2, const float* __restrict__ ba2,
                  float* __restrict__ out) {
    const int g = blockIdx.x;
    const int tid = threadIdx.x;
    const int lane = tid & 31, wid = tid >> 5;

    __shared__ int sS, sE;
    __shared__ float red[32];
    __shared__ float s_bcast;
    __shared__ float pooled[64];

    if (tid == 0) {
        // lower_bound(batch, g) and lower_bound(batch, g+1)
        int lo = 0, hi = Nn;
        while (lo < hi) { int mid = (lo + hi) >> 1; if (batch[mid] < g) lo = mid + 1; else hi = mid; }
        sS = lo;
        hi = Nn;
        while (lo < hi) { int mid = (lo + hi) >> 1; if (batch[mid] < g + 1) lo = mid + 1; else hi = mid; }
        sE = lo;
    }
    __syncthreads();
    const int s = sS, e = sE;
    const int count = e - s;

    // ---- pass 1: c_i and block max ----
    float wc[16];
#pragma unroll
    for (int q = 0; q < 16; q++) wc[q] = Wc[q];
    float bias = bc[0];

    float lmax = NEG_INF;
    for (int i = s + tid; i < e; i += 256) {
        float cv = bias;
#pragma unroll
        for (int q = 0; q < 4; q++) {
            float4 c4 = __ldg(&clo4[(size_t)i * 4 + q]);
            cv += c4.x * wc[q * 4 + 0] + c4.y * wc[q * 4 + 1] + c4.z * wc[q * 4 + 2] + c4.w * wc[q * 4 + 3];
        }
        g_c[i] = cv;
        lmax = fmaxf(lmax, cv);
    }
#pragma unroll
    for (int o = 16; o > 0; o >>= 1) lmax = fmaxf(lmax, __shfl_xor_sync(0xffffffffu, lmax, o));
    if (lane == 0) red[wid] = lmax;
    __syncthreads();
    if (tid == 0) {
        float m = red[0];
#pragma unroll
        for (int q = 1; q < 8; q++) m = fmaxf(m, red[q]);
        s_bcast = m;
    }
    __syncthreads();
    const float cmax = s_bcast;

    // ---- pass 2: exp + sum ----
    float lsum = 0.f;
    for (int i = s + tid; i < e; i += 256) {
        float ev = expf(g_c[i] - cmax);
        g_e[i] = ev;
        lsum += ev;
    }
#pragma unroll
    for (int o = 16; o > 0; o >>= 1) lsum += __shfl_xor_sync(0xffffffffu, lsum, o);
    if (lane == 0) red[wid] = lsum;
    __syncthreads();
    if (tid == 0) {
        float m = 0.f;
#pragma unroll
        for (int q = 0; q < 8; q++) m += red[q];
        s_bcast = m;
    }
    __syncthreads();
    const float denom = s_bcast;
    const float scale = (count > 0) ? ((float)count / denom) : 0.f;

    // ---- pass 3: pooled[f] = max_i (p_i * h3[i][f]) ----
    const int f = tid & 63;        // feature
    const int grp = tid >> 6;      // 4 node groups
    float lm = NEG_INF;
    for (int i = s + grp; i < e; i += 4) {
        float p = g_e[i] * scale;
        lm = fmaxf(lm, p * __ldg(&h3[(size_t)i * 64 + f]));
    }
    __syncthreads();               // red[] reuse barrier
    __shared__ float pgrp[4][64];
    pgrp[grp][f] = lm;
    __syncthreads();
    if (tid < 64) {
        float m = fmaxf(fmaxf(pgrp[0][tid], pgrp[1][tid]), fmaxf(pgrp[2][tid], pgrp[3][tid]));
        pooled[tid] = (count > 0) ? m : 0.f;   // empty graph -> 0 (isfinite clamp)
    }
    __syncthreads();

    // ---- final MLP: 64 -> 16 (relu) -> 1 ----
    if (tid < 16) {
        float sj = ba1[tid];
        for (int ff = 0; ff < 64; ff++) sj += pooled[ff] * Wa1[ff * 16 + tid];
        sj = fmaxf(sj, 0.f) * Wa2[tid];
#pragma unroll
        for (int o = 8; o > 0; o >>= 1) sj += __shfl_down_sync(0x0000ffffu, sj, o, 16);
        if (tid == 0) out[g] = sj + ba2[0];
    }
}

// ---------------- launch ----------------
extern "C" void kernel_launch(void* const* d_in, const int* in_sizes, int n_in,
                              void* d_out, int out_size) {
    const float* x     = (const float*)d_in[0];
    const int*   ei    = (const int*)d_in[1];
    const int*   batch = (const int*)d_in[2];
    const float* clo   = (const float*)d_in[3];
    const float* W1l = (const float*)d_in[4];
    const float* b1l = (const float*)d_in[5];
    const float* W1r = (const float*)d_in[6];
    const float* W2l = (const float*)d_in[7];
    const float* b2l = (const float*)d_in[8];
    const float* W2r = (const float*)d_in[9];
    const float* W3l = (const float*)d_in[10];
    const float* b3l = (const float*)d_in[11];
    const float* W3r = (const float*)d_in[12];
    const float* Wc  = (const float*)d_in[13];
    const float* bc  = (const float*)d_in[14];
    const float* Wa1 = (const float*)d_in[15];
    const float* ba1 = (const float*)d_in[16];
    const float* Wa2 = (const float*)d_in[17];
    const float* ba2 = (const float*)d_in[18];
    float* out = (float*)d_out;

    float* agg; cudaGetSymbolAddress((void**)&agg, g_agg);
    float* h1;  cudaGetSymbolAddress((void**)&h1, g_h1);
    float* h2;  cudaGetSymbolAddress((void**)&h2, g_h2);
    float* h3;  cudaGetSymbolAddress((void**)&h3, g_h3);

    const int TB = 256;
    const int SCAN_BLOCKS = (Nn + 1023) / 1024;  // 98

    // ---- CSR build (by dst) ----
    zero_deg_kernel<<<(Nn + TB - 1) / TB, TB>>>();
    hist_kernel<<<(Ee + TB - 1) / TB, TB>>>(ei);
    scan_a_kernel<<<SCAN_BLOCKS, 1024>>>();
    scan_c_kernel<<<SCAN_BLOCKS, 1024>>>(SCAN_BLOCKS);
    csr_scatter_kernel<<<(Ee + TB - 1) / TB, TB>>>(ei);

    // ---- layer 1 (K = 128) ----
    agg_max128<<<(Nn * 32 + TB - 1) / TB, TB>>>((const float4*)x, (float4*)agg);
    sage_gemm<128><<<(Nn + 63) / 64, TB>>>(agg, x, W1l, b1l, W1r, h1);

    // ---- layer 2 (K = 64) ----
    agg_max64<<<(Nn * 32 + TB - 1) / TB, TB>>>((const float2*)h1, (float2*)agg);
    sage_gemm<64><<<(Nn + 63) / 64, TB>>>(agg, h1, W2l, b2l, W2r, h2);

    // ---- layer 3 (K = 64) ----
    agg_max64<<<(Nn * 32 + TB - 1) / TB, TB>>>((const float2*)h2, (float2*)agg);
    sage_gemm<64><<<(Nn + 63) / 64, TB>>>(agg, h2, W3l, b3l, W3r, h3);

    // ---- fused attention pooling + readout ----
    fused_pool_kernel<<<GG, 256>>>((const float4*)clo, Wc, bc, batch, h3,
                                   Wa1, ba1, Wa2, ba2, out);
}